// round 8
// baseline (speedup 1.0000x reference)
#include <cuda_runtime.h>

#define NN 10
#define MM 22
#define RR 2
#define NPAIR 55
#define TPB 160     // 5 warps: warp g owns rows {g, 9-g} = 11 pairs
#define BPB 64      // 64 batches per block: each lane handles (lane, lane+32)

__device__ float4 gcoef[NPAIR][MM];   // (A_r0, A_r1, B_r0, B_r1), alpha folded at m==0

// ---- One-shot coefficient build: softmax over literal selectors + alpha fold ----
__global__ void tl_build(const float* __restrict__ sel, const float* __restrict__ alog) {
    int idx = blockIdx.x * blockDim.x + threadIdx.x;
    if (idx >= NPAIR * MM) return;
    int p = idx / MM, m = idx - p * MM;
    int i = 0, rem = p;
    while (rem >= NN - i) { rem -= NN - i; i++; }
    int j = i + rem;
    float Av[RR], Bv[RR];
#pragma unroll
    for (int r = 0; r < RR; r++) {
        const float* s = sel + (size_t)((((i * NN + j) * RR + r) * MM + m) * 3);
        float x0 = s[0] * 1.25f, x1 = s[1] * 1.25f, x2 = s[2] * 1.25f;  // /LIT_TEMP
        float mx = fmaxf(x0, fmaxf(x1, x2));
        float e0 = __expf(x0 - mx), e1 = __expf(x1 - mx), e2 = __expf(x2 - mx);
        float inv = 1.0f / (e0 + e1 + e2);
        float s0 = e0 * inv, s1 = e1 * inv, s2 = e2 * inv;
        float A = s0 + s2, Bc = s1 - s2;       // lit = A + B*u
        if (m == 0) {                           // fold alpha = sigmoid(alog)
            float a = alog[(i * NN + j) * RR + r];
            float alpha = 1.0f / (1.0f + __expf(-a));
            A *= alpha; Bc *= alpha;
        }
        Av[r] = A; Bv[r] = Bc;
    }
    gcoef[p][m] = make_float4(Av[0], Av[1], Bv[0], Bv[1]);
}

// ---- Main kernel ----
__global__ void __launch_bounds__(TPB)
tl_main(const float* __restrict__ pred,   // (B, M)
        float* __restrict__ out,          // (B, N, N)
        int B) {
    __shared__ float wtile[BPB][101];      // 25.9 KB raw w tile (pad 101: conflict-free)
    __shared__ float rinvt[BPB][11];       // 2.8 KB per-(batch,row) 1/rowsum
    __shared__ float psm[BPB][MM + 1];     // 5.9 KB staged pred (pad 23: conflict-free)

    // Stage this block's 64x22 pred slab, coalesced
    {
        const float* gp = pred + (size_t)blockIdx.x * BPB * MM;
        int nelem = BPB * MM;
        long gmax = (long)B * MM - (long)blockIdx.x * BPB * MM;
        if (nelem > gmax) nelem = (int)gmax;
        for (int t = threadIdx.x; t < nelem; t += TPB) {
            int bb = t / MM, m = t - bb * MM;
            psm[bb][m] = __ldg(gp + t);
        }
    }
    __syncthreads();

    const int lane = threadIdx.x & 31;
    const int g    = threadIdx.x >> 5;           // warp id 0..4
    const int bA   = lane;                       // local batch A
    const int bB   = lane + 32;                  // local batch B

    // u for both batches, registers (conflict-free LDS: stride 23)
    float uA[MM], uB[MM];
#pragma unroll
    for (int m = 0; m < MM; m++) { uA[m] = psm[bA][m]; uB[m] = psm[bB][m]; }

    // ---- Phase 1: warp g computes full rows i = g and i = 9-g for 64 batches ----
#pragma unroll 1
    for (int rr = 0; rr < 2; rr++) {
        int i  = (rr == 0) ? g : (NN - 1 - g);
        int pb = i * NN - (i * (i - 1)) / 2;     // index of pair (i,i)
        int np = NN - i;
        float sumA = 0.0f, sumB = 0.0f;
        float* wrA = &wtile[bA][i * NN + i];
        float* wrB = &wtile[bB][i * NN + i];
#pragma unroll 1
        for (int jj = 0; jj < np; jj++) {
            const float4* cp = gcoef[pb + jj];
            // 4 scalar product chains: (batch, r) — coefficient scalars come
            // straight from the warp-uniform float4 (1 L1 wavefront per load).
            float pA0 = 1.0f, pA1 = 1.0f, pB0 = 1.0f, pB1 = 1.0f;
#pragma unroll
            for (int m = 0; m < MM; m++) {
                float4 c = __ldg(cp + m);        // (A0, A1, B0, B1)
                pA0 *= fmaf(c.z, uA[m], c.x);
                pA1 *= fmaf(c.w, uA[m], c.y);
                pB0 *= fmaf(c.z, uB[m], c.x);
                pB1 *= fmaf(c.w, uB[m], c.y);
            }
            // g = 1 - (1-c0)(1-c1) = c0 + c1 - c0*c1 ; w = clamp(g)^2
            float gA = pA0 + pA1 - pA0 * pA1;
            float gB = pB0 + pB1 - pB0 * pB1;
            float cA = fmaxf(gA, 1e-6f);
            float cB = fmaxf(gB, 1e-6f);
            float wA = cA * cA, wB = cB * cB;
            wrA[jj] = wA; sumA += wA;
            wrB[jj] = wB; sumB += wB;
        }
        rinvt[bA][i] = 1.0f / sumA;              // each (batch,row) written once
        rinvt[bB][i] = 1.0f / sumB;
    }
    __syncthreads();

    // ---- Phase 2: coalesced, normalized write-out with lower-triangle zeros ----
    int bmax = B - blockIdx.x * BPB;
    if (bmax > BPB) bmax = BPB;
    int emax = bmax * (NN * NN);
    float* ob = out + (size_t)blockIdx.x * (BPB * NN * NN);
#pragma unroll 1
    for (int e = threadIdx.x; e < emax; e += TPB) {
        int bb  = e / 100, c = e - bb * 100;
        int row = c / 10,  col = c - row * 10;
        float v = (col >= row) ? wtile[bb][c] * rinvt[bb][row] : 0.0f;
        ob[e] = v;
    }
}

extern "C" void kernel_launch(void* const* d_in, const int* in_sizes, int n_in,
                              void* d_out, int out_size) {
    const float* pred = (const float*)d_in[0];   // (B, M)
    const float* sel  = (const float*)d_in[1];   // (N, N, R, M, 3)
    const float* alog = (const float*)d_in[2];   // (N, N, R)
    float* out = (float*)d_out;                  // (B, N, N)
    int B = in_sizes[0] / MM;
    tl_build<<<10, 128>>>(sel, alog);            // 1210 entries, one-shot
    int blocks = (B + BPB - 1) / BPB;            // 256 blocks of 160 threads
    tl_main<<<blocks, TPB>>>(pred, out, B);
}

// round 9
// speedup vs baseline: 2.1004x; 2.1004x over previous
#include <cuda_runtime.h>

#define NN 10
#define MM 22
#define RR 2
#define NPAIR 55
#define TPB 256     // 8 warps; warp w owns pairs [w*7, w*7+7) (last warp 6) — 55 total
#define BPB 32      // one batch per lane

typedef unsigned long long u64;

__device__ ulonglong2 gcoef[NPAIR][MM];   // packed (A_r0,A_r1 | B_r0,B_r1), alpha folded at m==0

__constant__ int PAIR_CELL[NPAIR] = {
  0,1,2,3,4,5,6,7,8,9,
  11,12,13,14,15,16,17,18,19,
  22,23,24,25,26,27,28,29,
  33,34,35,36,37,38,39,
  44,45,46,47,48,49,
  55,56,57,58,59,
  66,67,68,69,
  77,78,79,
  88,89,
  99};

__device__ __forceinline__ u64 pack2(float x, float y) {
    u64 r; asm("mov.b64 %0, {%1, %2};" : "=l"(r) : "f"(x), "f"(y)); return r;
}
__device__ __forceinline__ void unpack2(u64 v, float& x, float& y) {
    asm("mov.b64 {%0, %1}, %2;" : "=f"(x), "=f"(y) : "l"(v));
}
__device__ __forceinline__ u64 fma2(u64 a, u64 b, u64 c) {
    u64 d; asm("fma.rn.f32x2 %0, %1, %2, %3;" : "=l"(d) : "l"(a), "l"(b), "l"(c)); return d;
}
__device__ __forceinline__ u64 mul2(u64 a, u64 b) {
    u64 d; asm("mul.rn.f32x2 %0, %1, %2;" : "=l"(d) : "l"(a), "l"(b)); return d;
}
__device__ __forceinline__ u64 one2() { return 0x3f8000003f800000ULL; }

// ---- One-shot coefficient build: softmax over literal selectors + alpha fold ----
__global__ void tl_build(const float* __restrict__ sel, const float* __restrict__ alog) {
    int idx = blockIdx.x * blockDim.x + threadIdx.x;
    if (idx >= NPAIR * MM) return;
    int p = idx / MM, m = idx - p * MM;
    int i = 0, rem = p;
    while (rem >= NN - i) { rem -= NN - i; i++; }
    int j = i + rem;
    float Av[RR], Bv[RR];
#pragma unroll
    for (int r = 0; r < RR; r++) {
        const float* s = sel + (size_t)((((i * NN + j) * RR + r) * MM + m) * 3);
        float x0 = s[0] * 1.25f, x1 = s[1] * 1.25f, x2 = s[2] * 1.25f;  // /LIT_TEMP
        float mx = fmaxf(x0, fmaxf(x1, x2));
        float e0 = __expf(x0 - mx), e1 = __expf(x1 - mx), e2 = __expf(x2 - mx);
        float inv = 1.0f / (e0 + e1 + e2);
        float s0 = e0 * inv, s1 = e1 * inv, s2 = e2 * inv;
        float A = s0 + s2, Bc = s1 - s2;       // lit = A + B*u
        if (m == 0) {                           // fold alpha = sigmoid(alog)
            float a = alog[(i * NN + j) * RR + r];
            float alpha = 1.0f / (1.0f + __expf(-a));
            A *= alpha; Bc *= alpha;
        }
        Av[r] = A; Bv[r] = Bc;
    }
    ulonglong2 v;
    v.x = pack2(Av[0], Av[1]);
    v.y = pack2(Bv[0], Bv[1]);
    gcoef[p][m] = v;
}

// ---- Main kernel ----
__global__ void __launch_bounds__(TPB, 4)
tl_main(const float* __restrict__ pred,   // (B, M)
        float* __restrict__ out,          // (B, N, N)
        int B) {
    __shared__ ulonglong2 sh[NPAIR][MM];   // 19.4 KB coefficients
    __shared__ float wtile[BPB][101];      // 12.9 KB raw w tile (pad 101: conflict-free)
    __shared__ float rinvt[BPB][11];       // 1.4 KB per-(batch,row) 1/rowsum
    __shared__ float psm[BPB][MM + 1];     // 2.9 KB staged pred (pad 23: conflict-free)

    // Coefficient table gmem -> smem (coalesced LDG.128)
    {
        const ulonglong2* gsrc = &gcoef[0][0];
        ulonglong2* sdst = &sh[0][0];
        for (int idx = threadIdx.x; idx < NPAIR * MM; idx += TPB) sdst[idx] = gsrc[idx];
    }
    // Stage this block's 32x22 pred slab, coalesced
    {
        const float* gp = pred + (size_t)blockIdx.x * BPB * MM;
        int nelem = BPB * MM;
        long gmax = (long)B * MM - (long)blockIdx.x * BPB * MM;
        if (nelem > gmax) nelem = (int)gmax;
        for (int t = threadIdx.x; t < nelem; t += TPB) {
            int bb = t / MM, m = t - bb * MM;
            psm[bb][m] = __ldg(gp + t);
        }
    }
    __syncthreads();

    const int lane = threadIdx.x & 31;
    const int w    = threadIdx.x >> 5;           // warp 0..7

    // u from smem, duplicated into packed f32x2 regs (stride 23: conflict-free)
    u64 u2[MM];
#pragma unroll
    for (int m = 0; m < MM; m++) {
        float v = psm[lane][m];
        u2[m] = pack2(v, v);
    }

    // ---- Phase 1: warp w computes pairs [w*7, min(w*7+7, 55)) for 32 batches ----
    {
        int p0 = w * 7;
        int p1 = p0 + 7; if (p1 > NPAIR) p1 = NPAIR;
#pragma unroll 1
        for (int p = p0; p < p1; p++) {
            const ulonglong2* cp = sh[p];
            u64 accA = one2(), accB = one2();    // even/odd m chains for ILP
#pragma unroll
            for (int m = 0; m < MM; m += 2) {
                ulonglong2 c0 = cp[m];
                ulonglong2 c1 = cp[m + 1];
                accA = mul2(accA, fma2(c0.y, u2[m],     c0.x));  // lit = B*u + A (both r)
                accB = mul2(accB, fma2(c1.y, u2[m + 1], c1.x));
            }
            float c0f, c1f;
            unpack2(mul2(accA, accB), c0f, c1f); // c_r = alpha_r * clause_r
            float gg = c0f + c1f - c0f * c1f;    // 1 - (1-c0)(1-c1)
            float gc = fmaxf(gg, 1e-6f);
            wtile[lane][PAIR_CELL[p]] = gc * gc; // exp(log(g)/0.5) == g^2
        }
    }
    __syncthreads();

    // ---- Phase 2: row sums -> 1/rowsum (320 (batch,row) cells, strided) ----
#pragma unroll 1
    for (int t = threadIdx.x; t < BPB * NN; t += TPB) {
        int bb = t & 31, row = t >> 5;
        const float* cells = &wtile[bb][row * NN];
        float s = 0.0f;
#pragma unroll 1
        for (int j = row; j < NN; j++) s += cells[j];
        rinvt[bb][row] = 1.0f / s;
    }
    __syncthreads();

    // ---- Phase 3: coalesced, normalized write-out with lower-triangle zeros ----
    int bmax = B - blockIdx.x * BPB;
    if (bmax > BPB) bmax = BPB;
    int emax = bmax * (NN * NN);
    float* ob = out + (size_t)blockIdx.x * (BPB * NN * NN);
#pragma unroll 1
    for (int e = threadIdx.x; e < emax; e += TPB) {
        int bb  = e / 100, c = e - bb * 100;
        int row = c / 10,  col = c - row * 10;
        float v = (col >= row) ? wtile[bb][c] * rinvt[bb][row] : 0.0f;
        ob[e] = v;
    }
}

extern "C" void kernel_launch(void* const* d_in, const int* in_sizes, int n_in,
                              void* d_out, int out_size) {
    const float* pred = (const float*)d_in[0];   // (B, M)
    const float* sel  = (const float*)d_in[1];   // (N, N, R, M, 3)
    const float* alog = (const float*)d_in[2];   // (N, N, R)
    float* out = (float*)d_out;                  // (B, N, N)
    int B = in_sizes[0] / MM;
    tl_build<<<10, 128>>>(sel, alog);            // 1210 entries, one-shot
    int blocks = (B + BPB - 1) / BPB;            // 512 blocks, 4 blocks/SM, single wave
    tl_main<<<blocks, TPB>>>(pred, out, B);
}